// round 12
// baseline (speedup 1.0000x reference)
#include <cuda_runtime.h>
#include <math.h>
#include <float.h>

#define BB 2
#define MM 256
#define DD 256
#define DE 64
#define TP 257
#define WM_RS 320
#define GRID 256
#define NT 256
#define NCTR 8
#define PER_CTR (GRID/NCTR)   // 32 arrivals per counter

typedef unsigned long long u64;

__device__ __forceinline__ u64 ffma2(u64 a, u64 b, u64 c) {
    u64 d; asm("fma.rn.f32x2 %0,%1,%2,%3;" : "=l"(d) : "l"(a), "l"(b), "l"(c)); return d;
}
__device__ __forceinline__ float2 unpack2(u64 p) {
    float2 r; asm("mov.b64 {%0,%1},%2;" : "=f"(r.x), "=f"(r.y) : "l"(p)); return r;
}

// ---------------- device scratch ----------------
__device__ __align__(256) float g_WcP[8][DD*DD];     // Wc j-partials
__device__ __align__(256) float g_nfP[4][BB*MM*DD];  // nfproj j-partials
__device__ __align__(256) float g_u[DD];
__device__ __align__(256) float g_nfb[DD];
__device__ __align__(256) float g_c1[1];
__device__ __align__(256) float g_aspdot[32];
__device__ __align__(256) float g_f0q[32*DD];
__device__ __align__(256) float g_fused[32*DD];
__device__ __align__(256) float g_wn[32*512];
__device__ __align__(256) int   g_list[32*512];
__device__ __align__(256) int   g_cnt[32];
__device__ __align__(128) unsigned g_ctrs[NCTR*32];  // one counter per 128B line

// ---------------- shared layout ----------------
struct SGemm { float As[32][68]; float Bs[32][68]; };
struct SQp   { float xa[DD]; float f0s[DD]; float us[DD];
               float wdep[DE]; float s_l[512]; int list[512]; };
struct SP2   { float dsr[96][64]; float wns[512]; int list[512];
               float fpart[8][32]; };
union USm { SGemm g; SQp q; SP2 p2; float cat[2*DD]; float misc[1024]; };

// ---------------- hierarchical grid barrier (monotonic, wrap-safe) ----------------
__device__ __forceinline__ void gbar() {
    __syncthreads();
    if (threadIdx.x == 0) {
        __threadfence();
        const int c = blockIdx.x & (NCTR - 1);
        const unsigned v = atomicAdd(&g_ctrs[c*32], 1u) + 1u;
        const unsigned epoch  = (v - 1u) / PER_CTR;       // all counters advance in lockstep epochs
        const unsigned target = (epoch + 1u) * PER_CTR;
        #pragma unroll 1
        for (int cc = 0; cc < NCTR; cc++) {
            unsigned cur;
            while (true) {
                asm volatile("ld.acquire.gpu.u32 %0, [%1];"
                             : "=r"(cur) : "l"(&g_ctrs[cc*32]) : "memory");
                if ((int)(cur - target) >= 0) break;
                asm volatile("nanosleep.u32 128;");
            }
        }
    }
    __syncthreads();
}

// ---------------- block reductions ----------------
__device__ __forceinline__ float bsum256(float v, float* red) {
    #pragma unroll
    for (int o = 16; o > 0; o >>= 1) v += __shfl_down_sync(0xffffffffu, v, o);
    if ((threadIdx.x & 31) == 0) red[threadIdx.x >> 5] = v;
    __syncthreads();
    if (threadIdx.x < 8) {
        v = red[threadIdx.x];
        #pragma unroll
        for (int o = 4; o > 0; o >>= 1) v += __shfl_down_sync(0xffu, v, o);
        if (threadIdx.x == 0) red[0] = v;
    }
    __syncthreads();
    float r = red[0];
    __syncthreads();
    return r;
}
__device__ __forceinline__ float bmax256(float v, float* red) {
    #pragma unroll
    for (int o = 16; o > 0; o >>= 1) v = fmaxf(v, __shfl_down_sync(0xffffffffu, v, o));
    if ((threadIdx.x & 31) == 0) red[threadIdx.x >> 5] = v;
    __syncthreads();
    if (threadIdx.x < 8) {
        v = red[threadIdx.x];
        #pragma unroll
        for (int o = 4; o > 0; o >>= 1) v = fmaxf(v, __shfl_down_sync(0xffu, v, o));
        if (threadIdx.x == 0) red[0] = v;
    }
    __syncthreads();
    float r = red[0];
    __syncthreads();
    return r;
}

// ---------------- persistent kernel ----------------
__global__ void __launch_bounds__(NT, 2) fused_all(
    const float* __restrict__ features, const float* __restrict__ dep,
    const int*   __restrict__ adj,      const int*   __restrict__ asp_start,
    const float* __restrict__ Wz,       const float* __restrict__ bz,
    const float* __restrict__ Wa,       const float* __restrict__ Wm,
    const float* __restrict__ Wh,       float* __restrict__ out)
{
    __shared__ __align__(16) USm sm;
    __shared__ float s_red[8];
    __shared__ int   s_w[8];

    const int bid = blockIdx.x, tid = threadIdx.x;

    // ================= P0 =================
    if (bid < 128) {
        // ---- Wc partial: tile 64x64, j-chunk of 32, 4x4 register tiling
        const int t = bid >> 3, jc = bid & 7;
        const int k0 = (t >> 2) * 64, d0 = (t & 3) * 64;
        const int j0 = jc * 32;
        #pragma unroll
        for (int p = 0; p < 2; p++) {
            const int idx = p*NT + tid;
            const int lj = idx >> 4, lk4 = idx & 15;
            *(float4*)&sm.g.As[lj][lk4*4] =
                *(const float4*)&Wz[(size_t)(j0 + lj)*DD + k0 + lk4*4];
        }
        #pragma unroll
        for (int p = 0; p < 2; p++) {
            const int idx = p*NT + tid;
            const int d = idx >> 3, jq = idx & 7;
            const float4 v = *(const float4*)&Wm[(size_t)(d0 + d)*WM_RS + DE + j0 + jq*4];
            sm.g.Bs[jq*4+0][d] = v.x;
            sm.g.Bs[jq*4+1][d] = v.y;
            sm.g.Bs[jq*4+2][d] = v.z;
            sm.g.Bs[jq*4+3][d] = v.w;
        }
        __syncthreads();
        const int am = tid & 15, bd = tid >> 4;
        float acc[4][4] = {};
        #pragma unroll
        for (int j = 0; j < 32; j++) {
            const float4 a4 = *(const float4*)&sm.g.As[j][4*am];
            const float4 b4 = *(const float4*)&sm.g.Bs[j][4*bd];
            const float av[4] = {a4.x, a4.y, a4.z, a4.w};
            const float bv[4] = {b4.x, b4.y, b4.z, b4.w};
            #pragma unroll
            for (int r = 0; r < 4; r++)
                #pragma unroll
                for (int c = 0; c < 4; c++)
                    acc[r][c] = fmaf(av[r], bv[c], acc[r][c]);
        }
        #pragma unroll
        for (int r = 0; r < 4; r++)
            *(float4*)&g_WcP[jc][(size_t)(k0 + 4*am + r)*DD + d0 + 4*bd] =
                make_float4(acc[r][0], acc[r][1], acc[r][2], acc[r][3]);
    }
    else if (bid < 160) {
        // ---- qprep-lite: f0q + aspdot + compaction + dep prefetch (NO u, NO scores)
        const int q = bid - 128;
        const int b = q >> 4;
        const int i = asp_start[b] + (q & 15);

        sm.q.xa[tid] = features[(size_t)(1 + i)*DD + tid];   // batch 0 asp row
        __syncthreads();

        // f0s = asp-row zf (8-lane row dots; uniform trip count)
        {
            const int grp = tid >> 3, l8 = tid & 7;
            const float4* x4 = (const float4*)sm.q.xa;
            #pragma unroll
            for (int rr = 0; rr < 8; rr++) {
                const int dr = grp*8 + rr;
                const float4* w4 = (const float4*)(Wz + (size_t)dr*DD);
                float o = 0.f;
                #pragma unroll
                for (int tt = 0; tt < 8; tt++) {
                    const float4 w = w4[tt*8 + l8], x = x4[tt*8 + l8];
                    o = fmaf(w.x, x.x, o); o = fmaf(w.y, x.y, o);
                    o = fmaf(w.z, x.z, o); o = fmaf(w.w, x.w, o);
                }
                o += __shfl_down_sync(0xffffffffu, o, 4, 8);
                o += __shfl_down_sync(0xffffffffu, o, 2, 8);
                o += __shfl_down_sync(0xffffffffu, o, 1, 8);
                if (l8 == 0) {
                    const float v = o + bz[dr];
                    sm.q.f0s[dr] = v;
                    g_f0q[q*DD + dr] = v;
                }
            }
        }
        __syncthreads();
        const float aspdot = bsum256(sm.q.f0s[tid] * Wa[DE + DD + tid], s_red);
        if (tid == 0) g_aspdot[q] = aspdot;

        // deterministic compaction
        const int lane = tid & 31, warp = tid >> 5;
        const int pred0 = adj[((size_t)b*MM + i)*MM + tid] != 0;
        const int pred1 = adj[((size_t)b*MM + tid)*MM + i] != 0;
        const unsigned m0 = __ballot_sync(0xffffffffu, pred0);
        const unsigned m1 = __ballot_sync(0xffffffffu, pred1);
        if (lane == 0) s_w[warp] = __popc(m0) + __popc(m1);
        __syncthreads();
        int base = 0;
        #pragma unroll
        for (int w = 0; w < 8; w++) if (w < warp) base += s_w[w];
        const unsigned ltm = (1u << lane) - 1u;
        if (pred0) g_list[q*512 + base + __popc(m0 & ltm)] = tid;
        if (pred1) g_list[q*512 + base + __popc(m0) + __popc(m1 & ltm)] = tid + MM;
        int n = 0;
        #pragma unroll
        for (int w = 0; w < 8; w++) n += s_w[w];
        if (tid == 0) g_cnt[q] = n;
        __syncthreads();

        // dep prefetch (DRAM -> L2) for listed rows
        for (int idx = tid; idx < 2*n; idx += NT) {
            const int j = idx >> 1, h = idx & 1;
            const int kk = g_list[q*512 + j];
            const int row = (kk < MM) ? i : kk - MM;
            const int col = (kk < MM) ? kk : i;
            const float* p = dep + (((size_t)b*MM + row)*MM + col)*DE + h*32;
            asm volatile("prefetch.global.L2 [%0];" :: "l"(p));
        }
    }
    else if (bid == 160) {
        // ---- u[k] = sum_j Wz[j][k]*Wa[64+j];  c1 = bz . Wa[64:320]
        sm.misc[tid] = Wa[DE + tid];
        __syncthreads();
        float s = 0.f;
        #pragma unroll 16
        for (int j = 0; j < DD; j++)
            s = fmaf(Wz[(size_t)j*DD + tid], sm.misc[j], s);
        g_u[tid] = s;
        const float c = bsum256(bz[tid] * sm.misc[tid], s_red);
        if (tid == 0) g_c1[0] = c;
    }
    else if (bid == 161) {
        // ---- nfb[d] = sum_j bz[j] * Wm[d][64+j]
        sm.misc[tid] = bz[tid];
        __syncthreads();
        const int rg8 = tid >> 3, l8 = tid & 7;
        for (int pass = 0; pass < 8; pass++) {
            const int dr = pass*32 + rg8;
            const float4* w4 = (const float4*)(Wm + (size_t)dr*WM_RS + DE);
            float s = 0.f;
            #pragma unroll
            for (int tt = 0; tt < 8; tt++) {
                const float4 w = w4[tt*8 + l8];
                const int jb = (tt*8 + l8)*4;
                s = fmaf(w.x, sm.misc[jb+0], s); s = fmaf(w.y, sm.misc[jb+1], s);
                s = fmaf(w.z, sm.misc[jb+2], s); s = fmaf(w.w, sm.misc[jb+3], s);
            }
            s += __shfl_down_sync(0xffffffffu, s, 4, 8);
            s += __shfl_down_sync(0xffffffffu, s, 2, 8);
            s += __shfl_down_sync(0xffffffffu, s, 1, 8);
            if (l8 == 0) g_nfb[dr] = s;
        }
    }
    else if (bid < 178) {
        // ---- copy features -> out (warms features in L2)
        const int cb = bid - 162;
        const float4* src = (const float4*)features;
        float4* d4 = (float4*)out;
        const int total = BB*TP*DD/4;   // 32896
        for (int x = cb*NT + tid; x < total; x += 16*NT) d4[x] = src[x];
    }
    else if (bid < 196) {
        // ---- prefetch Wh into L2 (warm for P3)
        const int gidx = (bid - 178)*NT + tid;
        if (gidx < 4096)
            asm volatile("prefetch.global.L2 [%0];" :: "l"(Wh + (size_t)gidx*32));
    }

    gbar();   // ================= barrier 1 =================

    // ================= P1: nfproj partials (Wc summed inline) + scores =================
    if (bid < 128) {
        const int tt = bid >> 2, jc = bid & 3;
        const int r0 = (tt >> 2) * 64, d0 = (tt & 3) * 64;
        const int b = r0 >> 8, m0 = r0 & 255;
        const int j0 = jc * 64;
        const int am = tid & 15, bd = tid >> 4;
        float acc[4][4] = {};
        #pragma unroll
        for (int cc = 0; cc < 2; cc++) {
            const int jb = j0 + cc*32;
            __syncthreads();
            #pragma unroll
            for (int p = 0; p < 2; p++) {
                const int idx = p*NT + tid;
                const int r = idx >> 3, jq = idx & 7;
                const float4 v =
                    *(const float4*)&features[((size_t)b*TP + 1 + m0 + r)*DD + jb + jq*4];
                sm.g.As[jq*4+0][r] = v.x;
                sm.g.As[jq*4+1][r] = v.y;
                sm.g.As[jq*4+2][r] = v.z;
                sm.g.As[jq*4+3][r] = v.w;
            }
            // B: sum the 8 Wc j-partials inline (replaces the former P0.5 phase)
            #pragma unroll
            for (int p = 0; p < 2; p++) {
                const int idx = p*NT + tid;
                const int j = idx >> 4, dq = idx & 15;
                const size_t off = (size_t)(jb + j)*DD + d0 + dq*4;
                float4 s4 = *(const float4*)&g_WcP[0][off];
                #pragma unroll
                for (int h = 1; h < 8; h++) {
                    const float4 v = *(const float4*)&g_WcP[h][off];
                    s4.x += v.x; s4.y += v.y; s4.z += v.z; s4.w += v.w;
                }
                *(float4*)&sm.g.Bs[j][dq*4] = s4;
            }
            __syncthreads();
            #pragma unroll
            for (int j = 0; j < 32; j++) {
                const float4 a4 = *(const float4*)&sm.g.As[j][4*am];
                const float4 b4 = *(const float4*)&sm.g.Bs[j][4*bd];
                const float av[4] = {a4.x, a4.y, a4.z, a4.w};
                const float bv[4] = {b4.x, b4.y, b4.z, b4.w};
                #pragma unroll
                for (int r = 0; r < 4; r++)
                    #pragma unroll
                    for (int c = 0; c < 4; c++)
                        acc[r][c] = fmaf(av[r], bv[c], acc[r][c]);
            }
        }
        float4 nb = make_float4(0.f, 0.f, 0.f, 0.f);
        if (jc == 0) nb = *(const float4*)&g_nfb[d0 + 4*bd];
        #pragma unroll
        for (int r = 0; r < 4; r++)
            *(float4*)&g_nfP[jc][(size_t)(r0 + 4*am + r)*DD + d0 + 4*bd] =
                make_float4(acc[r][0] + nb.x, acc[r][1] + nb.y,
                            acc[r][2] + nb.z, acc[r][3] + nb.w);
    }
    else if (bid < 160) {
        // ---- scores + softmax for one query (dep/features warm in L2)
        const int q = bid - 128;
        const int b = q >> 4;
        const int i = asp_start[b] + (q & 15);
        const int n = g_cnt[q];

        sm.q.us[tid] = g_u[tid];
        if (tid < DE) sm.q.wdep[tid] = Wa[tid];
        for (int idx = tid; idx < n; idx += NT) sm.q.list[idx] = g_list[q*512 + idx];
        __syncthreads();

        const float cadd = g_c1[0] + g_aspdot[q];

        // per-key score: 8-lane groups, warp-uniform trip count
        {
            const int gg = tid >> 3, l8 = tid & 7;
            const float4* us4 = (const float4*)sm.q.us;
            const float4* wd4 = (const float4*)sm.q.wdep;
            for (int jj = 0; jj < n; jj += 32) {     // n is block-uniform
                const int j = jj + gg;
                const bool act = (j < n);
                const int kk = sm.q.list[act ? j : 0];
                const int krow = kk & (MM-1);
                const int row = (kk < MM) ? i : krow;
                const int col = (kk < MM) ? kk : i;
                const float4* x4 = (const float4*)&features[((size_t)b*TP + 1 + krow)*DD];
                float s = 0.f;
                #pragma unroll
                for (int tt = 0; tt < 8; tt++) {
                    const float4 x = x4[tt*8 + l8], u = us4[tt*8 + l8];
                    s = fmaf(x.x, u.x, s); s = fmaf(x.y, u.y, s);
                    s = fmaf(x.z, u.z, s); s = fmaf(x.w, u.w, s);
                }
                const float4* dp4 = (const float4*)&dep[(((size_t)b*MM + row)*MM + col)*DE];
                #pragma unroll
                for (int tt = 0; tt < 2; tt++) {
                    const float4 dv = dp4[tt*8 + l8], wv = wd4[tt*8 + l8];
                    s = fmaf(dv.x, wv.x, s); s = fmaf(dv.y, wv.y, s);
                    s = fmaf(dv.z, wv.z, s); s = fmaf(dv.w, wv.w, s);
                }
                s += __shfl_down_sync(0xffffffffu, s, 4, 8);
                s += __shfl_down_sync(0xffffffffu, s, 2, 8);
                s += __shfl_down_sync(0xffffffffu, s, 1, 8);
                if (act && l8 == 0) {
                    const float sc = s + cadd;
                    sm.q.s_l[j] = (sc > 0.f) ? sc : 0.01f * sc;
                }
            }
        }
        __syncthreads();

        // softmax -> normalized weights (compact)
        const float sv0 = (tid      < n) ? sm.q.s_l[tid]      : -FLT_MAX;
        const float sv1 = (tid + NT < n) ? sm.q.s_l[tid + NT] : -FLT_MAX;
        const float smax = bmax256(fmaxf(sv0, sv1), s_red);
        const float e0 = (tid      < n) ? expf(sv0 - smax) : 0.f;
        const float e1 = (tid + NT < n) ? expf(sv1 - smax) : 0.f;
        const float inv = 1.f / bsum256(e0 + e1, s_red);
        if (tid      < n) g_wn[q*512 + tid]      = e0 * inv;
        if (tid + NT < n) g_wn[q*512 + tid + NT] = e1 * inv;
    }

    gbar();   // ================= barrier 2 =================

    // ================= P2: message =================
    if (bid < 256) {
        const int q = bid >> 3, dc = bid & 7;
        const int b = q >> 4;
        const int i = asp_start[b] + (q & 15);
        const int n = g_cnt[q];
        const int kg = tid >> 5, dl = tid & 31;
        const int d = dc*32 + dl;

        for (int idx = tid; idx < n; idx += NT) {
            sm.p2.list[idx] = g_list[q*512 + idx];
            sm.p2.wns[idx]  = g_wn[q*512 + idx];
        }
        // full Wm_dep row of this thread's d: DE=64 floats = 32 f32x2 packs
        u64 wp[32];
        {
            const ulonglong2* w2 = (const ulonglong2*)(Wm + (size_t)d*WM_RS);
            #pragma unroll
            for (int t2 = 0; t2 < 16; t2++) {
                const ulonglong2 v = w2[t2];
                wp[2*t2] = v.x; wp[2*t2 + 1] = v.y;
            }
        }
        __syncthreads();

        float acc = 0.f;
        for (int c0 = 0; c0 < n; c0 += 96) {
            const int nc = min(96, n - c0);
            __syncthreads();
            for (int idx = tid; idx < nc*16; idx += NT) {
                const int j = idx >> 4, e4 = idx & 15;
                const int kk = sm.p2.list[c0 + j];
                const int row = (kk < MM) ? i : kk - MM;
                const int col = (kk < MM) ? kk : i;
                *(float4*)&sm.p2.dsr[j][e4*4] =
                    ((const float4*)dep)[(((size_t)b*MM + row)*MM + col)*16 + e4];
            }
            __syncthreads();
            for (int jl = kg; jl < nc; jl += 8) {    // no shuffles inside: divergence OK
                const int pos = c0 + jl;
                const int kk = sm.p2.list[pos];
                const float wk = sm.p2.wns[pos];
                const int krow = kk & (MM-1);
                const size_t midx = ((size_t)b*MM + krow)*DD + d;
                const float mi = g_nfP[0][midx] + g_nfP[1][midx]
                               + g_nfP[2][midx] + g_nfP[3][midx];
                const ulonglong2* dr2 = (const ulonglong2*)&sm.p2.dsr[jl][0];
                u64 mA = 0, mB = 0, mC = 0, mD = 0;
                #pragma unroll
                for (int t2 = 0; t2 < 16; t2 += 2) {
                    const ulonglong2 v0 = dr2[t2];
                    const ulonglong2 v1 = dr2[t2 + 1];
                    mA = ffma2(v0.x, wp[2*t2],     mA);
                    mB = ffma2(v0.y, wp[2*t2 + 1], mB);
                    mC = ffma2(v1.x, wp[2*t2 + 2], mC);
                    mD = ffma2(v1.y, wp[2*t2 + 3], mD);
                }
                const float2 sA = unpack2(mA), sB = unpack2(mB);
                const float2 sC = unpack2(mC), sD = unpack2(mD);
                const float mval = mi + ((sA.x + sA.y) + (sB.x + sB.y))
                                      + ((sC.x + sC.y) + (sD.x + sD.y));
                acc = fmaf(wk, fmaxf(mval, 0.f), acc);
            }
        }
        sm.p2.fpart[kg][dl] = acc;
        __syncthreads();
        if (tid < 32) {
            float s = 0.f;
            #pragma unroll
            for (int g = 0; g < 8; g++) s += sm.p2.fpart[g][tid];
            g_fused[q*DD + dc*32 + tid] = s;
        }
    }

    gbar();   // ================= barrier 3 =================

    // ================= P3: output head =================
    if (bid < 256) {
        const int q = bid >> 3, rg = bid & 7;
        const int b = q >> 4;
        const int i = asp_start[b] + (q & 15);
        sm.cat[tid]      = g_fused[q*DD + tid];
        sm.cat[DD + tid] = g_f0q[q*DD + tid];
        __syncthreads();

        const int warp = tid >> 5, lane = tid & 31;
        const int rsub = lane >> 3, l8 = lane & 7;
        const int dr = rg*32 + warp*4 + rsub;
        const ulonglong2* wrow = (const ulonglong2*)(Wh + (size_t)dr*2*DD);
        const ulonglong2* cat2 = (const ulonglong2*)sm.cat;
        u64 oA = 0, oB = 0;
        #pragma unroll
        for (int tt = 0; tt < 16; tt++) {
            const int idx = tt*8 + l8;
            const ulonglong2 wv = wrow[idx];
            const ulonglong2 cv = cat2[idx];
            oA = ffma2(wv.x, cv.x, oA);
            oB = ffma2(wv.y, cv.y, oB);
        }
        const float2 a = unpack2(oA), bb = unpack2(oB);
        float o = (a.x + a.y) + (bb.x + bb.y);
        o += __shfl_down_sync(0xffffffffu, o, 4, 8);
        o += __shfl_down_sync(0xffffffffu, o, 2, 8);
        o += __shfl_down_sync(0xffffffffu, o, 1, 8);
        if (l8 == 0)
            out[((size_t)b*TP + 1 + i)*DD + dr] = fmaxf(o, 0.f);
    }
}

// ---------------- launcher ----------------
extern "C" void kernel_launch(void* const* d_in, const int* in_sizes, int n_in,
                              void* d_out, int out_size)
{
    const float* features  = (const float*)d_in[0];
    const float* dep       = (const float*)d_in[1];
    const int*   adj       = (const int*)  d_in[2];
    const int*   asp_start = (const int*)  d_in[3];
    const float* Wz        = (const float*)d_in[5];
    const float* bz        = (const float*)d_in[6];
    const float* Wa        = (const float*)d_in[7];
    const float* Wm        = (const float*)d_in[8];
    const float* Wh        = (const float*)d_in[9];
    float* out = (float*)d_out;

    fused_all<<<GRID, NT>>>(features, dep, adj, asp_start,
                            Wz, bz, Wa, Wm, Wh, out);
}

// round 13
// speedup vs baseline: 1.3117x; 1.3117x over previous
#include <cuda_runtime.h>
#include <math.h>
#include <float.h>

#define BB 2
#define MM 256
#define DD 256
#define DE 64
#define TP 257
#define WM_RS 320
#define GRID 148
#define NT 256
#define NCTR 4
#define PER_CTR (GRID/NCTR)   // 37 arrivals per counter

typedef unsigned long long u64;

__device__ __forceinline__ u64 ffma2(u64 a, u64 b, u64 c) {
    u64 d; asm("fma.rn.f32x2 %0,%1,%2,%3;" : "=l"(d) : "l"(a), "l"(b), "l"(c)); return d;
}
__device__ __forceinline__ float2 unpack2(u64 p) {
    float2 r; asm("mov.b64 {%0,%1},%2;" : "=f"(r.x), "=f"(r.y) : "l"(p)); return r;
}

// ---------------- device scratch ----------------
__device__ __align__(256) float g_WcP[4][DD*DD];     // Wc j-partials (64-j chunks)
__device__ __align__(256) float g_nfP[4][BB*MM*DD];  // nfproj j-partials
__device__ __align__(256) float g_uP[8][DD];         // u j-partials (32-j chunks)
__device__ __align__(256) float g_nfb[DD];
__device__ __align__(256) float g_c1[1];
__device__ __align__(256) float g_aspdot[32];
__device__ __align__(256) float g_nfdot[BB*MM];
__device__ __align__(256) float g_f0q[32*DD];
__device__ __align__(256) float g_fused[32*DD];
__device__ __align__(256) int   g_list[32*512];
__device__ __align__(256) int   g_cnt[32];
__device__ __align__(128) unsigned g_ctrs[NCTR*32];

// ---------------- shared layout ----------------
struct SGemm { float As[32][68]; float Bs[32][68]; };
struct SQp   { float xa[DD]; float f0s[DD]; };
struct SP2   { float dsr[96][64]; float s_l[512]; float wns[512];
               int list[512]; float wdep[DE]; float fpart[4][64]; };
union USm { SGemm g; SQp q; SP2 p2; float cat[2*DD]; float misc[1024]; };

// ---------------- hierarchical grid barrier (monotonic, wrap-safe) ----------------
__device__ __forceinline__ void gbar() {
    __syncthreads();
    if (threadIdx.x == 0) {
        __threadfence();
        const int c = blockIdx.x & (NCTR - 1);
        const unsigned v = atomicAdd(&g_ctrs[c*32], 1u) + 1u;
        const unsigned epoch  = (v - 1u) / PER_CTR;
        const unsigned target = (epoch + 1u) * PER_CTR;
        #pragma unroll 1
        for (int cc = 0; cc < NCTR; cc++) {
            unsigned cur;
            while (true) {
                asm volatile("ld.acquire.gpu.u32 %0, [%1];"
                             : "=r"(cur) : "l"(&g_ctrs[cc*32]) : "memory");
                if ((int)(cur - target) >= 0) break;
                asm volatile("nanosleep.u32 64;");
            }
        }
    }
    __syncthreads();
}

// ---------------- block reductions ----------------
__device__ __forceinline__ float bsum256(float v, float* red) {
    #pragma unroll
    for (int o = 16; o > 0; o >>= 1) v += __shfl_down_sync(0xffffffffu, v, o);
    if ((threadIdx.x & 31) == 0) red[threadIdx.x >> 5] = v;
    __syncthreads();
    if (threadIdx.x < 8) {
        v = red[threadIdx.x];
        #pragma unroll
        for (int o = 4; o > 0; o >>= 1) v += __shfl_down_sync(0xffu, v, o);
        if (threadIdx.x == 0) red[0] = v;
    }
    __syncthreads();
    float r = red[0];
    __syncthreads();
    return r;
}
__device__ __forceinline__ float bmax256(float v, float* red) {
    #pragma unroll
    for (int o = 16; o > 0; o >>= 1) v = fmaxf(v, __shfl_down_sync(0xffffffffu, v, o));
    if ((threadIdx.x & 31) == 0) red[threadIdx.x >> 5] = v;
    __syncthreads();
    if (threadIdx.x < 8) {
        v = red[threadIdx.x];
        #pragma unroll
        for (int o = 4; o > 0; o >>= 1) v = fmaxf(v, __shfl_down_sync(0xffu, v, o));
        if (threadIdx.x == 0) red[0] = v;
    }
    __syncthreads();
    float r = red[0];
    __syncthreads();
    return r;
}

// ---------------- persistent kernel (NO reg cap: avoid P2 spills) ----------------
__global__ void __launch_bounds__(NT) fused_all(
    const float* __restrict__ features, const float* __restrict__ dep,
    const int*   __restrict__ adj,      const int*   __restrict__ asp_start,
    const float* __restrict__ Wz,       const float* __restrict__ bz,
    const float* __restrict__ Wa,       const float* __restrict__ Wm,
    const float* __restrict__ Wh,       float* __restrict__ out)
{
    __shared__ __align__(16) USm sm;
    __shared__ float s_red[8];
    __shared__ int   s_w[8];

    const int bid = blockIdx.x, tid = threadIdx.x;

    // ================= P0 =================
    if (bid < 64) {
        // ---- Wc partial: 64x64 tile, 64-j chunk (2 sub-chunks of 32), 4x4 reg tiling
        const int t = bid >> 2, jc = bid & 3;
        const int k0 = (t >> 2) * 64, d0 = (t & 3) * 64;
        const int am = tid & 15, bd = tid >> 4;
        float acc[4][4] = {};
        #pragma unroll
        for (int cc = 0; cc < 2; cc++) {
            const int jb = jc*64 + cc*32;
            __syncthreads();
            #pragma unroll
            for (int p = 0; p < 2; p++) {
                const int idx = p*NT + tid;
                const int lj = idx >> 4, lk4 = idx & 15;
                *(float4*)&sm.g.As[lj][lk4*4] =
                    *(const float4*)&Wz[(size_t)(jb + lj)*DD + k0 + lk4*4];
            }
            #pragma unroll
            for (int p = 0; p < 2; p++) {
                const int idx = p*NT + tid;
                const int d = idx >> 3, jq = idx & 7;
                const float4 v = *(const float4*)&Wm[(size_t)(d0 + d)*WM_RS + DE + jb + jq*4];
                sm.g.Bs[jq*4+0][d] = v.x;
                sm.g.Bs[jq*4+1][d] = v.y;
                sm.g.Bs[jq*4+2][d] = v.z;
                sm.g.Bs[jq*4+3][d] = v.w;
            }
            __syncthreads();
            #pragma unroll
            for (int j = 0; j < 32; j++) {
                const float4 a4 = *(const float4*)&sm.g.As[j][4*am];
                const float4 b4 = *(const float4*)&sm.g.Bs[j][4*bd];
                const float av[4] = {a4.x, a4.y, a4.z, a4.w};
                const float bv[4] = {b4.x, b4.y, b4.z, b4.w};
                #pragma unroll
                for (int r = 0; r < 4; r++)
                    #pragma unroll
                    for (int c = 0; c < 4; c++)
                        acc[r][c] = fmaf(av[r], bv[c], acc[r][c]);
            }
        }
        #pragma unroll
        for (int r = 0; r < 4; r++)
            *(float4*)&g_WcP[jc][(size_t)(k0 + 4*am + r)*DD + d0 + 4*bd] =
                make_float4(acc[r][0], acc[r][1], acc[r][2], acc[r][3]);
    }
    else if (bid < 96) {
        // ---- qprep-lite: f0q + aspdot + compaction + dep prefetch
        const int q = bid - 64;
        const int b = q >> 4;
        const int i = asp_start[b] + (q & 15);

        sm.q.xa[tid] = features[(size_t)(1 + i)*DD + tid];
        __syncthreads();

        {   // f0s = asp-row zf (8-lane row dots)
            const int grp = tid >> 3, l8 = tid & 7;
            const float4* x4 = (const float4*)sm.q.xa;
            #pragma unroll
            for (int rr = 0; rr < 8; rr++) {
                const int dr = grp*8 + rr;
                const float4* w4 = (const float4*)(Wz + (size_t)dr*DD);
                float o = 0.f;
                #pragma unroll
                for (int tt = 0; tt < 8; tt++) {
                    const float4 w = w4[tt*8 + l8], x = x4[tt*8 + l8];
                    o = fmaf(w.x, x.x, o); o = fmaf(w.y, x.y, o);
                    o = fmaf(w.z, x.z, o); o = fmaf(w.w, x.w, o);
                }
                o += __shfl_down_sync(0xffffffffu, o, 4, 8);
                o += __shfl_down_sync(0xffffffffu, o, 2, 8);
                o += __shfl_down_sync(0xffffffffu, o, 1, 8);
                if (l8 == 0) {
                    const float v = o + bz[dr];
                    sm.q.f0s[dr] = v;
                    g_f0q[q*DD + dr] = v;
                }
            }
        }
        __syncthreads();
        const float aspdot = bsum256(sm.q.f0s[tid] * Wa[DE + DD + tid], s_red);
        if (tid == 0) g_aspdot[q] = aspdot;

        // deterministic compaction
        const int lane = tid & 31, warp = tid >> 5;
        const int pred0 = adj[((size_t)b*MM + i)*MM + tid] != 0;
        const int pred1 = adj[((size_t)b*MM + tid)*MM + i] != 0;
        const unsigned m0 = __ballot_sync(0xffffffffu, pred0);
        const unsigned m1 = __ballot_sync(0xffffffffu, pred1);
        if (lane == 0) s_w[warp] = __popc(m0) + __popc(m1);
        __syncthreads();
        int base = 0;
        #pragma unroll
        for (int w = 0; w < 8; w++) if (w < warp) base += s_w[w];
        const unsigned ltm = (1u << lane) - 1u;
        if (pred0) g_list[q*512 + base + __popc(m0 & ltm)] = tid;
        if (pred1) g_list[q*512 + base + __popc(m0) + __popc(m1 & ltm)] = tid + MM;
        int n = 0;
        #pragma unroll
        for (int w = 0; w < 8; w++) n += s_w[w];
        if (tid == 0) g_cnt[q] = n;
        __syncthreads();

        for (int idx = tid; idx < 2*n; idx += NT) {
            const int j = idx >> 1, h = idx & 1;
            const int kk = g_list[q*512 + j];
            const int row = (kk < MM) ? i : kk - MM;
            const int col = (kk < MM) ? kk : i;
            const float* p = dep + (((size_t)b*MM + row)*MM + col)*DE + h*32;
            asm volatile("prefetch.global.L2 [%0];" :: "l"(p));
        }
    }
    else if (bid < 104) {
        // ---- u partial: chunk h of 32 j's
        const int h = bid - 96;
        if (tid < 32) sm.misc[tid] = Wa[DE + h*32 + tid];
        __syncthreads();
        const int k = tid;
        float s = 0.f;
        #pragma unroll
        for (int jj = 0; jj < 32; jj++)
            s = fmaf(Wz[(size_t)(h*32 + jj)*DD + k], sm.misc[jj], s);
        g_uP[h][k] = s;
        if (h == 0) {   // c1 = bz . Wa[64:320]
            const float c = bsum256(bz[tid] * Wa[DE + tid], s_red);
            if (tid == 0) g_c1[0] = c;
        }
    }
    else if (bid == 104) {
        // ---- nfb[d] = sum_j bz[j] * Wm[d][64+j]
        sm.misc[tid] = bz[tid];
        __syncthreads();
        const int rg8 = tid >> 3, l8 = tid & 7;
        for (int pass = 0; pass < 8; pass++) {
            const int dr = pass*32 + rg8;
            const float4* w4 = (const float4*)(Wm + (size_t)dr*WM_RS + DE);
            float s = 0.f;
            #pragma unroll
            for (int tt = 0; tt < 8; tt++) {
                const float4 w = w4[tt*8 + l8];
                const int jb = (tt*8 + l8)*4;
                s = fmaf(w.x, sm.misc[jb+0], s); s = fmaf(w.y, sm.misc[jb+1], s);
                s = fmaf(w.z, sm.misc[jb+2], s); s = fmaf(w.w, sm.misc[jb+3], s);
            }
            s += __shfl_down_sync(0xffffffffu, s, 4, 8);
            s += __shfl_down_sync(0xffffffffu, s, 2, 8);
            s += __shfl_down_sync(0xffffffffu, s, 1, 8);
            if (l8 == 0) g_nfb[dr] = s;
        }
    }
    else if (bid < 121) {
        // ---- copy features -> out (warms features in L2)
        const int cb = bid - 105;
        const float4* src = (const float4*)features;
        float4* d4 = (float4*)out;
        const int total = BB*TP*DD/4;   // 32896
        for (int x = cb*NT + tid; x < total; x += 16*NT) d4[x] = src[x];
    }
    else if (bid < 139) {
        // ---- prefetch Wh into L2
        const int gidx = (bid - 121)*NT + tid;
        if (gidx < 4096)
            asm volatile("prefetch.global.L2 [%0];" :: "l"(Wh + (size_t)gidx*32));
    }

    gbar();   // ================= barrier 1 =================

    // ================= P1: nfproj partials (Wc summed inline) + nfdot =================
    if (bid < 128) {
        const int tt = bid >> 2, jc = bid & 3;
        const int r0 = (tt >> 2) * 64, d0 = (tt & 3) * 64;
        const int b = r0 >> 8, m0 = r0 & 255;
        const int am = tid & 15, bd = tid >> 4;
        float acc[4][4] = {};
        #pragma unroll
        for (int cc = 0; cc < 2; cc++) {
            const int jb = jc*64 + cc*32;
            __syncthreads();
            #pragma unroll
            for (int p = 0; p < 2; p++) {
                const int idx = p*NT + tid;
                const int r = idx >> 3, jq = idx & 7;
                const float4 v =
                    *(const float4*)&features[((size_t)b*TP + 1 + m0 + r)*DD + jb + jq*4];
                sm.g.As[jq*4+0][r] = v.x;
                sm.g.As[jq*4+1][r] = v.y;
                sm.g.As[jq*4+2][r] = v.z;
                sm.g.As[jq*4+3][r] = v.w;
            }
            // B: sum the 4 Wc j-partials inline
            #pragma unroll
            for (int p = 0; p < 2; p++) {
                const int idx = p*NT + tid;
                const int j = idx >> 4, dq = idx & 15;
                const size_t off = (size_t)(jb + j)*DD + d0 + dq*4;
                float4 s4 = *(const float4*)&g_WcP[0][off];
                #pragma unroll
                for (int h = 1; h < 4; h++) {
                    const float4 v = *(const float4*)&g_WcP[h][off];
                    s4.x += v.x; s4.y += v.y; s4.z += v.z; s4.w += v.w;
                }
                *(float4*)&sm.g.Bs[j][dq*4] = s4;
            }
            __syncthreads();
            #pragma unroll
            for (int j = 0; j < 32; j++) {
                const float4 a4 = *(const float4*)&sm.g.As[j][4*am];
                const float4 b4 = *(const float4*)&sm.g.Bs[j][4*bd];
                const float av[4] = {a4.x, a4.y, a4.z, a4.w};
                const float bv[4] = {b4.x, b4.y, b4.z, b4.w};
                #pragma unroll
                for (int r = 0; r < 4; r++)
                    #pragma unroll
                    for (int c = 0; c < 4; c++)
                        acc[r][c] = fmaf(av[r], bv[c], acc[r][c]);
            }
        }
        float4 nb = make_float4(0.f, 0.f, 0.f, 0.f);
        if (jc == 0) nb = *(const float4*)&g_nfb[d0 + 4*bd];
        #pragma unroll
        for (int r = 0; r < 4; r++)
            *(float4*)&g_nfP[jc][(size_t)(r0 + 4*am + r)*DD + d0 + 4*bd] =
                make_float4(acc[r][0] + nb.x, acc[r][1] + nb.y,
                            acc[r][2] + nb.z, acc[r][3] + nb.w);
    }
    else if (bid < 132) {
        // ---- nfdot: 128 rows per block, 8-lane dots against u (partials summed)
        const int r0 = (bid - 128) * 128;
        {
            float s = 0.f;
            #pragma unroll
            for (int h = 0; h < 8; h++) s += g_uP[h][tid];
            sm.misc[tid] = s;
        }
        __syncthreads();
        const float4* us4 = (const float4*)sm.misc;
        const int rg8 = tid >> 3, l8 = tid & 7;
        for (int pass = 0; pass < 4; pass++) {
            const int row = r0 + pass*32 + rg8;
            const int b = row >> 8, ml = row & 255;
            const float4* x4 = (const float4*)&features[((size_t)b*TP + 1 + ml)*DD];
            float s = 0.f;
            #pragma unroll
            for (int tt = 0; tt < 8; tt++) {
                const float4 x = x4[tt*8 + l8], u = us4[tt*8 + l8];
                s = fmaf(x.x, u.x, s); s = fmaf(x.y, u.y, s);
                s = fmaf(x.z, u.z, s); s = fmaf(x.w, u.w, s);
            }
            s += __shfl_down_sync(0xffffffffu, s, 4, 8);
            s += __shfl_down_sync(0xffffffffu, s, 2, 8);
            s += __shfl_down_sync(0xffffffffu, s, 1, 8);
            if (l8 == 0) g_nfdot[b*MM + ml] = s;
        }
    }

    gbar();   // ================= barrier 2 =================

    // ================= P2: scores + softmax + message (R6 k2b pattern) =================
    if (bid < 128) {
        const int q = bid >> 2, dc = bid & 3;
        const int b = q >> 4;
        const int i = asp_start[b] + (q & 15);
        const int n = g_cnt[q];
        const int kg = tid >> 6, dl = tid & 63;
        const int d = dc*64 + dl;

        for (int idx = tid; idx < n; idx += NT) sm.p2.list[idx] = g_list[q*512 + idx];
        if (tid < DE) sm.p2.wdep[tid] = Wa[tid];
        // full Wm_dep row of this thread's d (registers; no launch-bounds cap -> no spill)
        u64 wp[32];
        {
            const ulonglong2* w2 = (const ulonglong2*)(Wm + (size_t)d*WM_RS);
            #pragma unroll
            for (int t2 = 0; t2 < 16; t2++) {
                const ulonglong2 v = w2[t2];
                wp[2*t2] = v.x; wp[2*t2 + 1] = v.y;
            }
        }
        __syncthreads();

        const float cadd = g_c1[0] + g_aspdot[q];

        // ---- scores (chunked staging; one thread per key, no shuffles) ----
        for (int c0 = 0; c0 < n; c0 += 96) {
            const int nc = min(96, n - c0);
            __syncthreads();
            for (int idx = tid; idx < nc*16; idx += NT) {
                const int j = idx >> 4, e4 = idx & 15;
                const int kk = sm.p2.list[c0 + j];
                const int row = (kk < MM) ? i : kk - MM;
                const int col = (kk < MM) ? kk : i;
                *(float4*)&sm.p2.dsr[j][e4*4] =
                    ((const float4*)dep)[(((size_t)b*MM + row)*MM + col)*16 + e4];
            }
            __syncthreads();
            for (int j = tid; j < nc; j += NT) {
                float s = 0.f;
                #pragma unroll
                for (int e4 = 0; e4 < 16; e4++) {
                    const float4 v = *(const float4*)&sm.p2.dsr[j][e4*4];
                    s = fmaf(v.x, sm.p2.wdep[4*e4+0], s); s = fmaf(v.y, sm.p2.wdep[4*e4+1], s);
                    s = fmaf(v.z, sm.p2.wdep[4*e4+2], s); s = fmaf(v.w, sm.p2.wdep[4*e4+3], s);
                }
                const int kk = sm.p2.list[c0 + j];
                s += g_nfdot[b*MM + (kk & (MM-1))] + cadd;
                sm.p2.s_l[c0 + j] = (s > 0.f) ? s : 0.01f * s;
            }
        }
        __syncthreads();

        // ---- softmax over n ----
        const float sv0 = (tid      < n) ? sm.p2.s_l[tid]      : -FLT_MAX;
        const float sv1 = (tid + NT < n) ? sm.p2.s_l[tid + NT] : -FLT_MAX;
        const float smax = bmax256(fmaxf(sv0, sv1), s_red);
        const float e0 = (tid      < n) ? expf(sv0 - smax) : 0.f;
        const float e1 = (tid + NT < n) ? expf(sv1 - smax) : 0.f;
        const float inv = 1.f / bsum256(e0 + e1, s_red);
        if (tid      < n) sm.p2.wns[tid]      = e0 * inv;
        if (tid + NT < n) sm.p2.wns[tid + NT] = e1 * inv;

        // ---- message ----
        float acc = 0.f;
        for (int c0 = 0; c0 < n; c0 += 96) {
            const int nc = min(96, n - c0);
            __syncthreads();
            for (int idx = tid; idx < nc*16; idx += NT) {
                const int j = idx >> 4, e4 = idx & 15;
                const int kk = sm.p2.list[c0 + j];
                const int row = (kk < MM) ? i : kk - MM;
                const int col = (kk < MM) ? kk : i;
                *(float4*)&sm.p2.dsr[j][e4*4] =
                    ((const float4*)dep)[(((size_t)b*MM + row)*MM + col)*16 + e4];
            }
            __syncthreads();
            for (int jl = kg; jl < nc; jl += 4) {    // no shuffles: divergence OK
                const int pos = c0 + jl;
                const int kk = sm.p2.list[pos];
                const float wk = sm.p2.wns[pos];
                const int krow = kk & (MM-1);
                const size_t midx = ((size_t)b*MM + krow)*DD + d;
                const float mi = g_nfP[0][midx] + g_nfP[1][midx]
                               + g_nfP[2][midx] + g_nfP[3][midx];
                const ulonglong2* dr2 = (const ulonglong2*)&sm.p2.dsr[jl][0];
                u64 mA = 0, mB = 0, mC = 0, mD = 0;
                #pragma unroll
                for (int t2 = 0; t2 < 16; t2 += 2) {
                    const ulonglong2 v0 = dr2[t2];
                    const ulonglong2 v1 = dr2[t2 + 1];
                    mA = ffma2(v0.x, wp[2*t2],     mA);
                    mB = ffma2(v0.y, wp[2*t2 + 1], mB);
                    mC = ffma2(v1.x, wp[2*t2 + 2], mC);
                    mD = ffma2(v1.y, wp[2*t2 + 3], mD);
                }
                const float2 sA = unpack2(mA), sB = unpack2(mB);
                const float2 sC = unpack2(mC), sD = unpack2(mD);
                const float mval = mi + ((sA.x + sA.y) + (sB.x + sB.y))
                                      + ((sC.x + sC.y) + (sD.x + sD.y));
                acc = fmaf(wk, fmaxf(mval, 0.f), acc);
            }
        }
        sm.p2.fpart[kg][dl] = acc;
        __syncthreads();
        if (tid < 64)
            g_fused[q*DD + dc*64 + tid] = sm.p2.fpart[0][tid] + sm.p2.fpart[1][tid]
                                        + sm.p2.fpart[2][tid] + sm.p2.fpart[3][tid];
    }

    gbar();   // ================= barrier 3 =================

    // ================= P3: output head (2 tasks per block) =================
    if (bid < 128) {
        #pragma unroll
        for (int rep = 0; rep < 2; rep++) {
            const int t = bid + rep*128;
            const int q = t >> 3, rg = t & 7;
            const int b = q >> 4;
            const int i = asp_start[b] + (q & 15);
            __syncthreads();
            sm.cat[tid]      = g_fused[q*DD + tid];
            sm.cat[DD + tid] = g_f0q[q*DD + tid];
            __syncthreads();

            const int warp = tid >> 5, lane = tid & 31;
            const int rsub = lane >> 3, l8 = lane & 7;
            const int dr = rg*32 + warp*4 + rsub;
            const ulonglong2* wrow = (const ulonglong2*)(Wh + (size_t)dr*2*DD);
            const ulonglong2* cat2 = (const ulonglong2*)sm.cat;
            u64 oA = 0, oB = 0;
            #pragma unroll
            for (int tt = 0; tt < 16; tt++) {
                const int idx = tt*8 + l8;
                const ulonglong2 wv = wrow[idx];
                const ulonglong2 cv = cat2[idx];
                oA = ffma2(wv.x, cv.x, oA);
                oB = ffma2(wv.y, cv.y, oB);
            }
            const float2 a = unpack2(oA), bb = unpack2(oB);
            float o = (a.x + a.y) + (bb.x + bb.y);
            o += __shfl_down_sync(0xffffffffu, o, 4, 8);
            o += __shfl_down_sync(0xffffffffu, o, 2, 8);
            o += __shfl_down_sync(0xffffffffu, o, 1, 8);
            if (l8 == 0)
                out[((size_t)b*TP + 1 + i)*DD + dr] = fmaxf(o, 0.f);
        }
    }
}

// ---------------- launcher ----------------
extern "C" void kernel_launch(void* const* d_in, const int* in_sizes, int n_in,
                              void* d_out, int out_size)
{
    const float* features  = (const float*)d_in[0];
    const float* dep       = (const float*)d_in[1];
    const int*   adj       = (const int*)  d_in[2];
    const int*   asp_start = (const int*)  d_in[3];
    const float* Wz        = (const float*)d_in[5];
    const float* bz        = (const float*)d_in[6];
    const float* Wa        = (const float*)d_in[7];
    const float* Wm        = (const float*)d_in[8];
    const float* Wh        = (const float*)d_in[9];
    float* out = (float*)d_out;

    fused_all<<<GRID, NT>>>(features, dep, adj, asp_start,
                            Wz, bz, Wa, Wm, Wh, out);
}